// round 1
// baseline (speedup 1.0000x reference)
#include <cuda_runtime.h>

// CRF loss: logZ - gold.  T=512, B=512, N=64 (fixed by problem instance).
// Inputs (metadata order): emit f32 (T,B,N), transitions f32 (N,N), strans f32 (N,),
// etrans f32 (N,), target i32 (T,B), mask (T,B) dtype runtime-detected.

#define TT 512
#define BB 512
#define NN 64
#define LOG2E 1.4426950408889634f
#define LN2F  0.6931471805599453f

__device__ float  g_E[NN * NN];   // e^{trans[i][j]}
__device__ int    g_len[BB];
__device__ double g_logZ;
__device__ double g_gold;

__device__ __forceinline__ float ex2f_(float x) {
    float y; asm("ex2.approx.ftz.f32 %0, %1;" : "=f"(y) : "f"(x)); return y;
}
__device__ __forceinline__ float lg2f_(float x) {
    float y; asm("lg2.approx.ftz.f32 %0, %1;" : "=f"(y) : "f"(x)); return y;
}
// packed 2x fp32 fma: d = a*b + d
__device__ __forceinline__ void fma2_(unsigned long long& d,
                                      unsigned long long a,
                                      unsigned long long b) {
    asm("fma.rn.f32x2 %0, %1, %2, %0;" : "+l"(d) : "l"(a), "l"(b));
}
__device__ __forceinline__ unsigned long long add2_(unsigned long long a,
                                                    unsigned long long b) {
    unsigned long long d;
    asm("add.rn.f32x2 %0, %1, %2;" : "=l"(d) : "l"(a), "l"(b));
    return d;
}

// ---------------- init: exp(trans), lengths from mask, zero accumulators ----
__global__ void k_init(const float* __restrict__ trans, const void* __restrict__ maskp) {
    int tid = blockIdx.x * blockDim.x + threadIdx.x;
    if (tid < NN * NN) g_E[tid] = ex2f_(LOG2E * trans[tid]);
    int b = tid - NN * NN;
    if (b >= 0 && b < BB) {
        // mask row t=0 is all-true (lengths >= 1): word0 identifies the dtype.
        unsigned w0 = ((const unsigned*)maskp)[0];
        int len = 0;
        if (w0 == 1u) {                       // int32 0/1
            const int* m = (const int*)maskp;
            for (int t = 0; t < TT; ++t) len += (m[t * BB + b] != 0);
        } else if (w0 == 0x3F800000u) {       // float 0/1
            const float* m = (const float*)maskp;
            for (int t = 0; t < TT; ++t) len += (m[t * BB + b] != 0.0f);
        } else {                              // bytes (bool)
            const unsigned char* m = (const unsigned char*)maskp;
            for (int t = 0; t < TT; ++t) len += (m[t * BB + b] != 0);
        }
        g_len[b] = len;
    }
    if (tid == 0) { g_logZ = 0.0; g_gold = 0.0; }
}

// ---------------- forward recurrence: one warp per batch chain ---------------
__global__ void __launch_bounds__(128, 1)
k_forward(const float* __restrict__ emit,
          const float* __restrict__ strans,
          const float* __restrict__ etrans) {
    // per-warp p broadcast buffer, duplicated pairs {p,p}, double-buffered
    __shared__ float4 pbuf[2][4][32];
    const int w = threadIdx.x >> 5;
    const int l = threadIdx.x & 31;
    const int b = blockIdx.x * 4 + w;

    // lane l owns output columns j = 2l, 2l+1: keep both E columns in registers
    unsigned long long Ereg[NN];
#pragma unroll
    for (int i = 0; i < NN; ++i)
        Ereg[i] = *(const unsigned long long*)(g_E + i * NN + 2 * l);

    const int len = g_len[b];
    const float* eb = emit + (size_t)b * NN + 2 * l;  // emit[t][b][2l] at eb + t*BB*NN

    // A = log2(e) * alpha  (work entirely in log2 domain)
    float2 e0 = *(const float2*)eb;
    float2 st = *(const float2*)(strans + 2 * l);
    float A0 = LOG2E * (e0.x + st.x);
    float A1 = LOG2E * (e0.y + st.y);

    // exact initial offset
    float m = fmaxf(A0, A1);
#pragma unroll
    for (int o = 16; o; o >>= 1) m = fmaxf(m, __shfl_xor_sync(0xffffffffu, m, o));
    float Moff = m;

    for (int t = 1; t < len; ++t) {
        float2 e = *(const float2*)(eb + (size_t)t * (BB * NN));  // prefetch early
        float p0 = ex2f_(A0 - Moff);
        float p1 = ex2f_(A1 - Moff);
        const int bufi = t & 1;
        pbuf[bufi][w][l] = make_float4(p0, p0, p1, p1);
        // next-step offset: lagged exact max, independent of the matvec below,
        // so its shfl-chain latency overlaps the FMA loop
        float mn = fmaxf(A0, A1);
        __syncwarp();
#pragma unroll
        for (int o = 16; o; o >>= 1) mn = fmaxf(mn, __shfl_xor_sync(0xffffffffu, mn, o));

        unsigned long long accE = 0ull, accO = 0ull;
        const ulonglong2* pb = (const ulonglong2*)pbuf[bufi][w];
#pragma unroll
        for (int k = 0; k < 32; ++k) {
            ulonglong2 q = pb[k];            // broadcast LDS.128: {p2k,p2k,p2k+1,p2k+1}
            fma2_(accE, q.x, Ereg[2 * k]);
            fma2_(accO, q.y, Ereg[2 * k + 1]);
        }
        unsigned long long acc = add2_(accE, accO);
        unsigned lo, hi;
        asm("mov.b64 {%0, %1}, %2;" : "=r"(lo), "=r"(hi) : "l"(acc));
        A0 = fmaf(LOG2E, e.x, Moff + lg2f_(__uint_as_float(lo)));
        A1 = fmaf(LOG2E, e.y, Moff + lg2f_(__uint_as_float(hi)));
        Moff = mn;
    }

    // logZ_b = ln sum_j exp(alpha_j + etrans_j)
    float2 et = *(const float2*)(etrans + 2 * l);
    float G0 = A0 + LOG2E * et.x;
    float G1 = A1 + LOG2E * et.y;
    float m2 = fmaxf(G0, G1);
#pragma unroll
    for (int o = 16; o; o >>= 1) m2 = fmaxf(m2, __shfl_xor_sync(0xffffffffu, m2, o));
    float s = ex2f_(G0 - m2) + ex2f_(G1 - m2);
#pragma unroll
    for (int o = 16; o; o >>= 1) s += __shfl_xor_sync(0xffffffffu, s, o);
    if (l == 0)
        atomicAdd(&g_logZ, (double)(LN2F * (m2 + lg2f_(s))));
}

// ---------------- gold path score ------------------------------------------
__global__ void k_gold(const float* __restrict__ emit,
                       const float* __restrict__ trans,
                       const float* __restrict__ strans,
                       const float* __restrict__ etrans,
                       const int* __restrict__ target) {
    int idx = blockIdx.x * blockDim.x + threadIdx.x;  // = t*BB + b
    int t = idx / BB;
    int b = idx - t * BB;
    float c = 0.0f;
    int len = g_len[b];
    if (t < len) {
        int tg = target[idx];
        c = emit[(size_t)idx * NN + tg];
        if (t > 0) c += trans[target[idx - BB] * NN + tg];
        if (t == 0) c += strans[tg];
        if (t == len - 1) c += etrans[tg];
    }
#pragma unroll
    for (int o = 16; o; o >>= 1) c += __shfl_xor_sync(0xffffffffu, c, o);
    if ((threadIdx.x & 31) == 0) atomicAdd(&g_gold, (double)c);
}

// ---------------- final ----------------------------------------------------
__global__ void k_final(float* __restrict__ out) {
    out[0] = (float)(g_logZ - g_gold);
}

extern "C" void kernel_launch(void* const* d_in, const int* in_sizes, int n_in,
                              void* d_out, int out_size) {
    const float* emit   = (const float*)d_in[0];
    const float* trans  = (const float*)d_in[1];
    const float* strans = (const float*)d_in[2];
    const float* etrans = (const float*)d_in[3];
    const int*   target = (const int*)d_in[4];
    const void*  mask   = d_in[5];
    (void)in_sizes; (void)n_in; (void)out_size;

    k_init<<<18, 256>>>(trans, mask);
    k_forward<<<128, 128>>>(emit, strans, etrans);
    k_gold<<<(TT * BB) / 256, 256>>>(emit, trans, strans, etrans, target);
    k_final<<<1, 1>>>((float*)d_out);
}

// round 2
// speedup vs baseline: 1.0163x; 1.0163x over previous
#include <cuda_runtime.h>

// CRF loss: logZ - gold.  T=512, B=512, N=64.
// Inputs: emit f32 (T,B,N), transitions f32 (N,N), strans f32 (N,), etrans f32 (N,),
// target i32 (T,B), mask (T,B) dtype runtime-detected (prefix mask: t < length).

#define TT 512
#define BB 512
#define NN 64
#define LOG2E 1.4426950408889634f
#define LN2F  0.6931471805599453f

#define FWD_BLOCKS  128
#define GOLD_BLOCKS 2048                 // (T*B)/128
#define TOT_BLOCKS  (FWD_BLOCKS + GOLD_BLOCKS)

__device__ __align__(16) float g_EpT[NN * NN];   // exp(trans)^T  : [j][i]
__device__ int      g_len[BB];
__device__ double   g_logZ;
__device__ double   g_gold;
__device__ unsigned g_done;

__device__ __forceinline__ float ex2f_(float x) {
    float y; asm("ex2.approx.ftz.f32 %0, %1;" : "=f"(y) : "f"(x)); return y;
}
__device__ __forceinline__ float lg2f_(float x) {
    float y; asm("lg2.approx.ftz.f32 %0, %1;" : "=f"(y) : "f"(x)); return y;
}
__device__ __forceinline__ void fma2_(unsigned long long& d,
                                      unsigned long long a,
                                      unsigned long long b) {
    asm("fma.rn.f32x2 %0, %1, %2, %0;" : "+l"(d) : "l"(a), "l"(b));
}
__device__ __forceinline__ unsigned long long add2_(unsigned long long a,
                                                    unsigned long long b) {
    unsigned long long d;
    asm("add.rn.f32x2 %0, %1, %2;" : "=l"(d) : "l"(a), "l"(b));
    return d;
}
__device__ __forceinline__ float pairsum_(unsigned long long a) {
    unsigned lo, hi;
    asm("mov.b64 {%0, %1}, %2;" : "=r"(lo), "=r"(hi) : "l"(a));
    return __uint_as_float(lo) + __uint_as_float(hi);
}

// mask dtype: 0=int32, 1=float32, 2=byte  (row t=0 is all-true since lengths>=1)
__device__ __forceinline__ int mask_kind(const void* maskp) {
    unsigned w0 = ((const unsigned*)maskp)[0];
    return (w0 == 1u) ? 0 : (w0 == 0x3F800000u ? 1 : 2);
}
__device__ __forceinline__ bool mask_at(const void* maskp, int kind, int idx) {
    if (kind == 0) return ((const int*)maskp)[idx] != 0;
    if (kind == 1) return ((const float*)maskp)[idx] != 0.0f;
    return ((const unsigned char*)maskp)[idx] != 0;
}

// ---------------- init: exp(trans)^T, lengths, zero accumulators ------------
__global__ void k_init(const float* __restrict__ trans, const void* __restrict__ maskp) {
    int tid = blockIdx.x * blockDim.x + threadIdx.x;
    if (tid < NN * NN) {
        int i = tid & (NN - 1);
        int j = tid >> 6;
        g_EpT[tid] = ex2f_(LOG2E * trans[i * NN + j]);   // g_EpT[j*64+i]
    }
    int b = tid - NN * NN;
    if (b >= 0 && b < BB) {
        int kind = mask_kind(maskp);
        int len = 0;
        for (int t = 0; t < TT; ++t) len += mask_at(maskp, kind, t * BB + b);
        g_len[b] = len;
    }
    if (tid == 0) { g_logZ = 0.0; g_gold = 0.0; g_done = 0u; }
}

// ---------------- fused forward + gold + final ------------------------------
__global__ void __launch_bounds__(128, 1)
k_main(const float* __restrict__ emit,
       const float* __restrict__ trans,
       const float* __restrict__ strans,
       const float* __restrict__ etrans,
       const int*   __restrict__ target,
       const void*  __restrict__ maskp,
       float*       __restrict__ out) {
    __shared__ unsigned long long pbuf[2][4][32];   // natural-pair p broadcast, dbl-buffered

    if (blockIdx.x < FWD_BLOCKS) {
        // ======== forward recurrence: one warp per chain ========
        const int w = threadIdx.x >> 5;
        const int l = threadIdx.x & 31;
        const int b = blockIdx.x * 4 + w;

        // lane l owns columns c0=2l, c1=2l+1; E columns in registers, i-pair packed
        ulonglong2 E0[16], E1[16];
        {
            const ulonglong2* ep0 = (const ulonglong2*)(g_EpT + (2 * l) * NN);
            const ulonglong2* ep1 = (const ulonglong2*)(g_EpT + (2 * l + 1) * NN);
#pragma unroll
            for (int k = 0; k < 16; ++k) { E0[k] = ep0[k]; E1[k] = ep1[k]; }
        }

        const int len = g_len[b];
        const float* eb = emit + (size_t)b * NN + 2 * l;

        float2 e0 = *(const float2*)eb;
        float2 st = *(const float2*)(strans + 2 * l);
        float A0 = LOG2E * (e0.x + st.x);
        float A1 = LOG2E * (e0.y + st.y);
        float Moff = __shfl_sync(0xffffffffu, A0, 0);   // any uniform offset is exact

#pragma unroll 2
        for (int t = 1; t < len; ++t) {
            float2 e = *(const float2*)(eb + (size_t)t * (BB * NN));
            float p0 = ex2f_(A0 - Moff);
            float p1 = ex2f_(A1 - Moff);
            unsigned long long pp;
            asm("mov.b64 %0, {%1, %2};" : "=l"(pp) : "f"(p0), "f"(p1));
            pbuf[t & 1][w][l] = pp;
            float Mn = __shfl_sync(0xffffffffu, A0, 0); // lagged offset, off critical path
            __syncwarp();

            const ulonglong2* pb = (const ulonglong2*)pbuf[t & 1][w];
            unsigned long long aA0 = 0, aA1 = 0, aA2 = 0, aA3 = 0;
            unsigned long long aB0 = 0, aB1 = 0, aB2 = 0, aB3 = 0;
#pragma unroll
            for (int m = 0; m < 16; m += 2) {
                ulonglong2 q = pb[m];
                ulonglong2 r = pb[m + 1];
                fma2_(aA0, q.x, E0[m].x);     fma2_(aA1, q.y, E0[m].y);
                fma2_(aB0, q.x, E1[m].x);     fma2_(aB1, q.y, E1[m].y);
                fma2_(aA2, r.x, E0[m + 1].x); fma2_(aA3, r.y, E0[m + 1].y);
                fma2_(aB2, r.x, E1[m + 1].x); fma2_(aB3, r.y, E1[m + 1].y);
            }
            float s0 = pairsum_(add2_(add2_(aA0, aA1), add2_(aA2, aA3)));
            float s1 = pairsum_(add2_(add2_(aB0, aB1), add2_(aB2, aB3)));
            A0 = fmaf(LOG2E, e.x, Moff + lg2f_(s0));
            A1 = fmaf(LOG2E, e.y, Moff + lg2f_(s1));
            Moff = Mn;
        }

        // logZ_b
        float2 et = *(const float2*)(etrans + 2 * l);
        float G0 = fmaf(LOG2E, et.x, A0);
        float G1 = fmaf(LOG2E, et.y, A1);
        float m2 = fmaxf(G0, G1);
#pragma unroll
        for (int o = 16; o; o >>= 1) m2 = fmaxf(m2, __shfl_xor_sync(0xffffffffu, m2, o));
        float s = ex2f_(G0 - m2) + ex2f_(G1 - m2);
#pragma unroll
        for (int o = 16; o; o >>= 1) s += __shfl_xor_sync(0xffffffffu, s, o);
        if (l == 0)
            atomicAdd(&g_logZ, (double)(LN2F * (m2 + lg2f_(s))));
    } else {
        // ======== gold path score (mask-derived endpoints, no g_len) ========
        int idx = (blockIdx.x - FWD_BLOCKS) * 128 + threadIdx.x;  // = t*BB + b
        int t = idx >> 9;
        int kind = mask_kind(maskp);
        float c = 0.0f;
        if (mask_at(maskp, kind, idx)) {
            int tg = target[idx];
            c = emit[(size_t)idx * NN + tg];
            if (t > 0) c += trans[target[idx - BB] * NN + tg];
            else       c += strans[tg];
            bool mnext = (t < TT - 1) && mask_at(maskp, kind, idx + BB);
            if (!mnext) c += etrans[tg];                 // t is the last valid step
        }
#pragma unroll
        for (int o = 16; o; o >>= 1) c += __shfl_xor_sync(0xffffffffu, c, o);
        if ((threadIdx.x & 31) == 0) atomicAdd(&g_gold, (double)c);
    }

    // ======== last-block writes the result ========
    __syncthreads();
    if (threadIdx.x == 0) {
        __threadfence();
        if (atomicAdd(&g_done, 1u) == TOT_BLOCKS - 1) {
            double lz = atomicAdd(&g_logZ, 0.0);
            double gd = atomicAdd(&g_gold, 0.0);
            out[0] = (float)(lz - gd);
        }
    }
}

extern "C" void kernel_launch(void* const* d_in, const int* in_sizes, int n_in,
                              void* d_out, int out_size) {
    const float* emit   = (const float*)d_in[0];
    const float* trans  = (const float*)d_in[1];
    const float* strans = (const float*)d_in[2];
    const float* etrans = (const float*)d_in[3];
    const int*   target = (const int*)d_in[4];
    const void*  mask   = d_in[5];
    (void)in_sizes; (void)n_in; (void)out_size;

    k_init<<<18, 256>>>(trans, mask);
    k_main<<<TOT_BLOCKS, 128>>>(emit, trans, strans, etrans, target, mask,
                                (float*)d_out);
}